// round 7
// baseline (speedup 1.0000x reference)
#include <cuda_runtime.h>
#include <cstdint>

// HH_Synaptic, Round 7: 2 chains per thread (stage-major interleave for
// explicit 2-way ILP across the serial recurrence), float2 coalesced I/O.
// 8192 threads = 128 blocks x 64; thread t -> b = t>>9, l = (t&511)*2.

#define N_DIM 2000
#define LH    512        // L/2 float2 groups per row
#define PF    4
#define CH    2

__device__ __forceinline__ float ex2f_(float x){ float r; asm("ex2.approx.f32 %0, %1;" : "=f"(r) : "f"(x)); return r; }
__device__ __forceinline__ float rcpf_(float x){ float r; asm("rcp.approx.f32 %0, %1;" : "=f"(r) : "f"(x)); return r; }

__device__ __forceinline__ uint64_t pk2(float lo, float hi){
    uint64_t r; asm("mov.b64 %0, {%1, %2};" : "=l"(r) : "f"(lo), "f"(hi)); return r;
}
__device__ __forceinline__ void upk2(float& lo, float& hi, uint64_t v){
    asm("mov.b64 {%0, %1}, %2;" : "=f"(lo), "=f"(hi) : "l"(v));
}
__device__ __forceinline__ uint64_t fma2_(uint64_t a, uint64_t b, uint64_t c){
    uint64_t d; asm("fma.rn.f32x2 %0, %1, %2, %3;" : "=l"(d) : "l"(a), "l"(b), "l"(c)); return d;
}
__device__ __forceinline__ uint64_t mul2_(uint64_t a, uint64_t b){
    uint64_t d; asm("mul.rn.f32x2 %0, %1, %2;" : "=l"(d) : "l"(a), "l"(b)); return d;
}
__device__ __forceinline__ uint64_t add2_(uint64_t a, uint64_t b){
    uint64_t d; asm("add.rn.f32x2 %0, %1, %2;" : "=l"(d) : "l"(a), "l"(b)); return d;
}

__global__ __launch_bounds__(64, 1)
void hh_synaptic_kernel(const float2* __restrict__ z, float2* __restrict__ out) {
    const int t  = blockIdx.x * blockDim.x + threadIdx.x;   // 0 .. 8191
    const int b  = t >> 9;
    const int gl = t & 511;

    const float2* zp = z   + (size_t)b * (N_DIM * LH) + gl;
    float2*       op = out + (size_t)b * (N_DIM * LH) + gl;

    const float LOG2E = 1.4426950408889634f;
    const float c9    = LOG2E / 9.0f;
    const float c12   = LOG2E / 12.0f;
    const float cAH   = 0.25f * expf(-56.0f / 12.0f);
    const float cSIG  = LOG2E / 3.0f;

    // Packed constants (lane0 = N-rail, lane1 = M-rail)
    const uint64_t C_off  = pk2(-25.0f, 35.0f);
    const uint64_t C_c9   = pk2(c9, c9);
    const uint64_t C_m1   = pk2(-1.0f, -1.0f);
    const uint64_t C_se   = pk2(0.02f, 0.182f);
    const uint64_t C_t    = pk2(0.002f, 0.124f);
    const uint64_t C_sc   = pk2(0.02f*0.02f, 0.02f*0.182f);
    const uint64_t C_001  = pk2(0.01f, 0.01f);

    // Singularity-patch constants: x' = kP*x + cP
    const float pN_ = 0.01f*(0.18f+0.08f),  pM_ = 0.01f*(1.638f+1.16f);
    const float kNp = (1.0f-pN_)/(1.0f+pN_), cNp = (0.02f*0.18f)/(1.0f+pN_);
    const float kMp = (1.0f-pM_)/(1.0f+pM_), cMp = (0.02f*1.638f)/(1.0f+pM_);

    // State (2 chains)
    float V[CH], h[CH], y[CH];
    uint64_t nm[CH];
    #pragma unroll
    for (int c = 0; c < CH; ++c) { V[c] = -70.0f; h[c] = 1.0f; y[c] = 0.0f; nm[c] = pk2(0.0f, 0.0f); }

    // k = 0 output (same constant both chains)
    {
        float e  = ex2f_(-(-70.0f + 20.0f) * cSIG);
        float s0 = rcpf_(1.0f + e);
        float2 o; o.x = s0; o.y = s0;
        op[0] = o;
    }

    // z prefetch ring (float2): step k consumes z row (k-1)
    float2 zbuf[PF];
    #pragma unroll
    for (int j = 0; j < PF; ++j)
        zbuf[j] = __ldg(zp + (size_t)j * LH);

    float2* ol = op + LH;

    #pragma unroll 2
    for (int k = 1; k < N_DIM; ++k) {
        float2 z2 = zbuf[0];
        #pragma unroll
        for (int j = 0; j < PF - 1; ++j) zbuf[j] = zbuf[j + 1];
        int pidx = min(k - 1 + PF, N_DIM - 1);
        zbuf[PF - 1] = __ldg(zp + (size_t)pidx * LH);

        float zc[CH] = { z2.x, z2.y };

        // ---- Stage B: y update (series rcp, p <= 0.011), both chains ----
        float yn[CH];
        #pragma unroll
        for (int c = 0; c < CH; ++c) {
            float pY = fmaf(0.01f, zc[c], 0.001f);
            float rY = fmaf(pY, fmaf(pY, 1.0f - pY, -1.0f), 1.0f);
            yn[c] = fmaf(zc[c], 0.02f, fmaf(-pY, y[c], y[c])) * rY;
        }

        // ---- Stage C: implicit V update, both chains ----
        float Vn[CH];
        #pragma unroll
        for (int c = 0; c < CH; ++c) {
            float n_, m_; upk2(n_, m_, nm[c]);
            float mm   = m_ * m_;
            float pow1 = (mm * m_) * (40.0f * h[c]);
            float n2   = n_ * n_;
            float pow2 = 35.0f * (n2 * n2);
            float G    = 0.01f * ((pow1 + pow2) + (0.3f + y[c]));
            float E    = fmaf(pow1, 55.0f, fmaf(pow2, -77.0f, -19.5f));
            float base = fmaf(0.02f, E, V[c] + 0.02f);
            Vn[c] = fmaf(-V[c], G, base) * rcpf_(1.0f + G);
        }

        // ---- Stage D: all ex2s, both chains ----
        uint64_t dv2[CH], e2[CH];
        float eHp[CH], eHm[CH];
        #pragma unroll
        for (int c = 0; c < CH; ++c) {
            uint64_t vv = pk2(Vn[c], Vn[c]);
            dv2[c] = add2_(vv, C_off);
            uint64_t ea = mul2_(dv2[c], C_c9);
            float ealo, eahi; upk2(ealo, eahi, ea);
            e2[c]  = pk2(ex2f_(ealo), ex2f_(eahi));
            eHp[c] = ex2f_(fmaf(Vn[c],  c12,  34.0f * c12));
            eHm[c] = ex2f_(fmaf(Vn[c], -c12, -34.0f * c12));
        }

        // ---- Stage E: fused N/M rails, both chains ----
        #pragma unroll
        for (int c = 0; c < CH; ++c) {
            uint64_t dv01 = mul2_(dv2[c], C_001);
            uint64_t D2   = add2_(e2[c], C_m1);
            uint64_t set2 = fma2_(C_se, e2[c], C_t);
            uint64_t q2   = mul2_(dv01, set2);
            uint64_t Dq2  = add2_(D2, q2);
            float dqlo, dqhi; upk2(dqlo, dqhi, Dq2);
            uint64_t r2   = pk2(rcpf_(dqlo), rcpf_(dqhi));
            uint64_t Dmq2 = fma2_(q2, C_m1, D2);
            uint64_t edv2 = mul2_(e2[c], dv2[c]);
            uint64_t num2 = fma2_(nm[c], Dmq2, mul2_(edv2, C_sc));
            uint64_t res2 = mul2_(num2, r2);

            float dvlo, dvhi; upk2(dvlo, dvhi, dv2[c]);
            float n_, m_; upk2(n_, m_, nm[c]);
            float rn, rm; upk2(rn, rm, res2);
            rn = (dvlo == 0.0f) ? fmaf(n_, kNp, cNp) : rn;
            rm = (dvhi == 0.0f) ? fmaf(m_, kMp, cMp) : rm;
            nm[c] = pk2(rn, rm);
        }

        // ---- Stage F: h gate + commit, both chains ----
        #pragma unroll
        for (int c = 0; c < CH; ++c) {
            float aH = cAH   * eHm[c];
            float bH = 0.25f * eHp[c];
            float pH = 0.01f * (aH + bH);
            h[c] = fmaf(aH, 0.02f, fmaf(-pH, h[c], h[c])) * rcpf_(1.0f + pH);
            y[c] = yn[c];
            V[c] = Vn[c];
        }

        // ---- Stage G: output sigmoid + store ----
        float sg[CH];
        #pragma unroll
        for (int c = 0; c < CH; ++c) {
            float e = ex2f_(fmaf(Vn[c], -cSIG, -20.0f * cSIG));
            sg[c] = rcpf_(1.0f + e);
        }
        float2 o; o.x = sg[0]; o.y = sg[1];
        *ol = o;
        ol += LH;
    }
}

extern "C" void kernel_launch(void* const* d_in, const int* in_sizes, int n_in,
                              void* d_out, int out_size) {
    const float2* z = (const float2*)d_in[0];
    float2* out = (float2*)d_out;
    // 16384 chains / 2 per thread = 8192 threads = 128 blocks x 64
    hh_synaptic_kernel<<<128, 64>>>(z, out);
}

// round 8
// speedup vs baseline: 1.5443x; 1.5443x over previous
#include <cuda_runtime.h>

// HH_Synaptic, Round 8: fully scalar (no f32x2 pack/unpack MOV tax),
// fused one-rcp gate algebra, shared exponential eM = eN * exp(60/9),
// series-reciprocal y gate. 1 chain/thread, 128 blocks x 128.

#define N_DIM 2000
#define L_DIM 1024
#define PF    4

__device__ __forceinline__ float ex2f_(float x){ float r; asm("ex2.approx.f32 %0, %1;" : "=f"(r) : "f"(x)); return r; }
__device__ __forceinline__ float rcpf_(float x){ float r; asm("rcp.approx.f32 %0, %1;" : "=f"(r) : "f"(x)); return r; }

__global__ __launch_bounds__(128, 1)
void hh_synaptic_kernel(const float* __restrict__ z, float* __restrict__ out) {
    const int idx = blockIdx.x * blockDim.x + threadIdx.x;   // 0 .. 16383
    const int b = idx >> 10;
    const int l = idx & (L_DIM - 1);

    const float* zp = z   + (size_t)b * (N_DIM * L_DIM) + l;
    float*       op = out + (size_t)b * (N_DIM * L_DIM) + l;

    const float LOG2E = 1.4426950408889634f;
    const float c9    = LOG2E / 9.0f;
    const float c12   = LOG2E / 12.0f;
    const float cAH   = 0.25f * expf(-56.0f / 12.0f);
    const float cSIG  = LOG2E / 3.0f;
    const float K_NM  = expf(60.0f / 9.0f);     // eM = eN * K_NM

    // Singularity-patch constants: x' = kP*x + cP (reference's exact-equality cases)
    const float pN_ = 0.01f*(0.18f+0.08f),  pM_ = 0.01f*(1.638f+1.16f);
    const float kNp = (1.0f-pN_)/(1.0f+pN_), cNp = (0.02f*0.18f)/(1.0f+pN_);
    const float kMp = (1.0f-pM_)/(1.0f+pM_), cMp = (0.02f*1.638f)/(1.0f+pM_);

    // State
    float V = -70.0f;
    float m = 0.0f, n = 0.0f, h = 1.0f, y = 0.0f;

    // k = 0 output
    {
        float e = ex2f_(-(V + 20.0f) * cSIG);
        op[0] = rcpf_(1.0f + e);
    }

    // z prefetch ring: step k consumes z index (k-1)
    float zbuf[PF];
    #pragma unroll
    for (int j = 0; j < PF; ++j)
        zbuf[j] = __ldg(zp + (size_t)j * L_DIM);

    float* ol = op + L_DIM;

    #pragma unroll 4
    for (int k = 1; k < N_DIM; ++k) {
        float zc = zbuf[0];
        #pragma unroll
        for (int j = 0; j < PF - 1; ++j) zbuf[j] = zbuf[j + 1];
        int pidx = min(k - 1 + PF, N_DIM - 1);
        zbuf[PF - 1] = __ldg(zp + (size_t)pidx * L_DIM);

        // ---- y update (independent of V path): series rcp, pY <= 0.011 ----
        float pY = fmaf(0.01f, zc, 0.001f);
        float rY = fmaf(pY, fmaf(pY, 1.0f - pY, -1.0f), 1.0f);   // 1 - p + p^2 - p^3
        float yn = fmaf(zc, 0.02f, fmaf(-pY, y, y)) * rY;

        // ---- implicit V update ----
        float mm   = m * m;
        float pow1 = (mm * m) * (40.0f * h);             // GNA*m^3*h
        float n2   = n * n;
        float pow2 = 35.0f * (n2 * n2);                  // GK*n^4
        float G    = 0.01f * ((pow1 + pow2) + (0.3f + y));
        float E    = fmaf(pow1, 55.0f, fmaf(pow2, -77.0f, -19.5f));
        float base = fmaf(0.02f, E, V + 0.02f);          // V + DT*(E+IAPP)
        float Vn   = fmaf(-V, G, base) * rcpf_(1.0f + G);

        // ---- exponentials: eM shares eN via constant ----
        float dv25 = Vn - 25.0f;
        float dv35 = Vn + 35.0f;
        float eN  = ex2f_(dv25 * c9);                    // exp((V-25)/9)
        float eM  = eN * K_NM;                           // exp((V+35)/9)
        float eHp = ex2f_(fmaf(Vn,  c12,  34.0f * c12));
        float eHm = ex2f_(fmaf(Vn, -c12, -34.0f * c12));

        // ---- N rail (fused single-rcp): x' = (0.02*s*dv*e + x*(D-q)) / (D+q) ----
        // D = e-1, q = 0.01*dv*(s*e + t);  N: s=0.02, t=0.002
        {
            float D   = eN - 1.0f;
            float set = fmaf(0.02f, eN, 0.002f);
            float q   = (0.01f * dv25) * set;
            float r   = rcpf_(D + q);
            float dvE = dv25 * eN;
            float num = fmaf(n, D - q, 4.0e-4f * dvE);   // 0.02*0.02 = 4e-4
            float res = num * r;
            n = (dv25 == 0.0f) ? fmaf(n, kNp, cNp) : res;
        }
        // ---- M rail: s=0.182, t=0.124 ----
        {
            float D   = eM - 1.0f;
            float set = fmaf(0.182f, eM, 0.124f);
            float q   = (0.01f * dv35) * set;
            float r   = rcpf_(D + q);
            float dvE = dv35 * eM;
            float num = fmaf(m, D - q, (0.02f*0.182f) * dvE);
            float res = num * r;
            m = (dv35 == 0.0f) ? fmaf(m, kMp, cMp) : res;
        }

        // ---- h gate (standard single-rcp) ----
        float aH = cAH   * eHm;
        float bH = 0.25f * eHp;
        float pH = 0.01f * (aH + bH);
        h = fmaf(aH, 0.02f, fmaf(-pH, h, h)) * rcpf_(1.0f + pH);
        y = yn;
        V = Vn;

        // ---- output sigmoid (off the recurrence) ----
        float e = ex2f_(fmaf(Vn, -cSIG, -20.0f * cSIG));
        *ol = rcpf_(1.0f + e);
        ol += L_DIM;
    }
}

extern "C" void kernel_launch(void* const* d_in, const int* in_sizes, int n_in,
                              void* d_out, int out_size) {
    const float* z = (const float*)d_in[0];
    float* out = (float*)d_out;
    hh_synaptic_kernel<<<128, 128>>>(z, out);
}